// round 14
// baseline (speedup 1.0000x reference)
#include <cuda_runtime.h>
#include <math.h>

#define N_PTS   524288
#define FD      8
#define NUM     128
#define MAXIT   5
#define EPSF    1e-6f
#define THRESH2 1e-8f        /* (1e-4)^2 */
#define NBLK    (N_PTS / 256)   /* 2048 */
#define TPB_SEG 256
#define TILE    768             /* 2*768*8*4 = 49152 B static smem (max) */
#define SLICE_OUT (N_PTS / NUM) /* 4096 labels per segsum block */

// ---- f32x2 packed helpers (sm_100+; each half independently .rn-rounded) ----
__device__ __forceinline__ unsigned long long pack2f(float a, float b) {
    unsigned long long r;
    asm("mov.b64 %0, {%1, %2};" : "=l"(r)
        : "r"(__float_as_uint(a)), "r"(__float_as_uint(b)));
    return r;
}
__device__ __forceinline__ unsigned long long addx2(unsigned long long a,
                                                    unsigned long long b) {
    unsigned long long r;
    asm("add.rn.f32x2 %0, %1, %2;" : "=l"(r) : "l"(a), "l"(b));
    return r;
}
__device__ __forceinline__ unsigned long long mulx2(unsigned long long a,
                                                    unsigned long long b) {
    unsigned long long r;
    asm("mul.rn.f32x2 %0, %1, %2;" : "=l"(r) : "l"(a), "l"(b));
    return r;
}
__device__ __forceinline__ void unpack2f(float& lo, float& hi, unsigned long long v) {
    unsigned x, y;
    asm("mov.b64 {%0, %1}, %2;" : "=r"(x), "=r"(y) : "l"(v));
    lo = __uint_as_float(x); hi = __uint_as_float(y);
}

// ---- device scratch (no allocations allowed) ----
__device__ float  g_centers[NUM * FD];
__device__ int    g_counts[NUM];     // zero at entry: zero-init + segsum resets
__device__ float  g_dsq[NUM];
__device__ int    g_labels[N_PTS];
__device__ int    g_converged;
__device__ int    g_ticket1;
__device__ int    g_ticket2;
__device__ __align__(16) float2 g_xy[N_PTS];  // packed first-2 coords (4 MB)
// counting-sort scratch
__device__ int    g_blockhist[NBLK * NUM];
__device__ int    g_blockpre[NBLK * NUM];
__device__ int    g_base[NUM];
__device__ int    g_total[NUM];
__device__ int    g_idx[N_PTS];

// ------------------------------------------------------------------
// Iteration-0 fused kernel: init globals (block 0) + pack xy coords +
// in-radius counts for the INITIAL centers. Gate arithmetic bit-exact:
// sp2 = rn(rn(dx*dx)+rn(dy*dy)), dx = rn(x + (-cx)); sp2 <= Y0.
__global__ void __launch_bounds__(256) countKernel0(const float* __restrict__ data,
                                                    const float* __restrict__ centers_in,
                                                    float Y0) {
    __shared__ unsigned long long ncx2[NUM / 2];
    __shared__ unsigned long long ncy2[NUM / 2];
    __shared__ int scnt[NUM];
    int t = threadIdx.x;

    if (blockIdx.x == 0) {               // fused init (visible at kernel boundary)
        #pragma unroll
        for (int j = t; j < NUM * FD; j += 256) g_centers[j] = centers_in[j];
        if (t == 0) { g_converged = 0; g_ticket1 = 0; g_ticket2 = 0; }
    }
    if (t < NUM / 2) {
        float cx0 = centers_in[(2 * t)     * FD];
        float cy0 = centers_in[(2 * t)     * FD + 1];
        float cx1 = centers_in[(2 * t + 1) * FD];
        float cy1 = centers_in[(2 * t + 1) * FD + 1];
        ncx2[t] = pack2f(-cx0, -cx1);
        ncy2[t] = pack2f(-cy0, -cy1);
    }
    if (t < NUM) scnt[t] = 0;
    __syncthreads();

    int idx  = blockIdx.x * 256 + t;
    float2 p = *(const float2*)(data + (size_t)idx * FD);
    g_xy[idx] = p;                       // fused pack
    unsigned long long pxx = pack2f(p.x, p.x);
    unsigned long long pyy = pack2f(p.y, p.y);
    int lane = t & 31;

    int c0 = 0, c1 = 0, c2 = 0, c3 = 0;
    #pragma unroll 4
    for (int ii = 0; ii < 32; ii++) {
        bool mine = (lane == ii);
        #pragma unroll
        for (int q = 0; q < 2; q++) {
            int pr = q * 32 + ii;
            unsigned long long dxv = addx2(pxx, ncx2[pr]);
            unsigned long long dyv = addx2(pyy, ncy2[pr]);
            unsigned long long sp2v = addx2(mulx2(dxv, dxv), mulx2(dyv, dyv));
            float slo, shi;
            unpack2f(slo, shi, sp2v);
            unsigned m0 = __ballot_sync(0xffffffffu, slo <= Y0);
            unsigned m1 = __ballot_sync(0xffffffffu, shi <= Y0);
            int p0 = __popc(m0), p1 = __popc(m1);
            if (mine) {
                if (q == 0) { c0 += p0; c1 += p1; }
                else        { c2 += p0; c3 += p1; }
            }
        }
    }
    atomicAdd(&scnt[2 * lane],      c0);
    atomicAdd(&scnt[2 * lane + 1],  c1);
    atomicAdd(&scnt[64 + 2 * lane], c2);
    atomicAdd(&scnt[65 + 2 * lane], c3);
    __syncthreads();
    if (t < NUM) atomicAdd(&g_counts[t], scnt[t]);
}

// ------------------------------------------------------------------
// Per-center in-radius counts for iterations 1+ (identical arithmetic).
__global__ void __launch_bounds__(256) countKernel(float Y0) {
    if (g_converged) return;
    __shared__ unsigned long long ncx2[NUM / 2];
    __shared__ unsigned long long ncy2[NUM / 2];
    __shared__ int scnt[NUM];
    int t = threadIdx.x;
    if (t < NUM / 2) {
        float cx0 = g_centers[(2 * t)     * FD];
        float cy0 = g_centers[(2 * t)     * FD + 1];
        float cx1 = g_centers[(2 * t + 1) * FD];
        float cy1 = g_centers[(2 * t + 1) * FD + 1];
        ncx2[t] = pack2f(-cx0, -cx1);
        ncy2[t] = pack2f(-cy0, -cy1);
    }
    if (t < NUM) scnt[t] = 0;
    __syncthreads();

    int idx  = blockIdx.x * 256 + t;
    float2 p = g_xy[idx];
    unsigned long long pxx = pack2f(p.x, p.x);
    unsigned long long pyy = pack2f(p.y, p.y);
    int lane = t & 31;

    int c0 = 0, c1 = 0, c2 = 0, c3 = 0;
    #pragma unroll 4
    for (int ii = 0; ii < 32; ii++) {
        bool mine = (lane == ii);
        #pragma unroll
        for (int q = 0; q < 2; q++) {
            int pr = q * 32 + ii;
            unsigned long long dxv = addx2(pxx, ncx2[pr]);
            unsigned long long dyv = addx2(pyy, ncy2[pr]);
            unsigned long long sp2v = addx2(mulx2(dxv, dxv), mulx2(dyv, dyv));
            float slo, shi;
            unpack2f(slo, shi, sp2v);
            unsigned m0 = __ballot_sync(0xffffffffu, slo <= Y0);
            unsigned m1 = __ballot_sync(0xffffffffu, shi <= Y0);
            int p0 = __popc(m0), p1 = __popc(m1);
            if (mine) {
                if (q == 0) { c0 += p0; c1 += p1; }
                else        { c2 += p0; c3 += p1; }
            }
        }
    }
    atomicAdd(&scnt[2 * lane],      c0);
    atomicAdd(&scnt[2 * lane + 1],  c1);
    atomicAdd(&scnt[64 + 2 * lane], c2);
    atomicAdd(&scnt[65 + 2 * lane], c3);
    __syncthreads();
    if (t < NUM) atomicAdd(&g_counts[t], scnt[t]);
}

// ------------------------------------------------------------------
// Assignment: faithful reference fp arithmetic (proven form).
__global__ void __launch_bounds__(256) assignKernel(const float* __restrict__ data,
                                                    float Y0) {
    if (g_converged) return;
    __shared__ float4 sc[NUM * 2];
    __shared__ int    shist[NUM];
    int t = threadIdx.x;

    {   // centers with "enough" gate baked into coord 0
        float4 v = ((const float4*)g_centers)[t];
        if ((t & 1) == 0) {
            if (g_counts[t >> 1] <= 1) v.x += 1e9f;
        }
        sc[t] = v;
    }
    if (t < NUM) shist[t] = 0;
    __syncthreads();

    int idx = blockIdx.x * 256 + t;
    float4 p0 = ((const float4*)data)[2 * idx];
    float4 p1 = ((const float4*)data)[2 * idx + 1];

    float dval = 1000.0f;
    int   label = -1;

    for (int i = 0; i < NUM; i++) {
        float4 c0 = sc[2 * i];
        float dx0 = p0.x - c0.x;
        float dx1 = p0.y - c0.y;
        float sp2 = __fadd_rn(__fmul_rn(dx0, dx0), __fmul_rn(dx1, dx1));
        bool need = (sp2 <= Y0) && (dval > 0.0f);
        if (__any_sync(0xffffffffu, need)) {
            float4 c1 = sc[2 * i + 1];
            float t0 = __fadd_rn(dx0, EPSF);
            float t1 = __fadd_rn(dx1, EPSF);
            float t2 = __fadd_rn(p0.z - c0.z, EPSF);
            float t3 = __fadd_rn(p0.w - c0.w, EPSF);
            float t4 = __fadd_rn(p1.x - c1.x, EPSF);
            float t5 = __fadd_rn(p1.y - c1.y, EPSF);
            float t6 = __fadd_rn(p1.z - c1.z, EPSF);
            float t7 = __fadd_rn(p1.w - c1.w, EPSF);
            float s = __fmul_rn(t0, t0);
            s = __fadd_rn(s, __fmul_rn(t1, t1));
            s = __fadd_rn(s, __fmul_rn(t2, t2));
            s = __fadd_rn(s, __fmul_rn(t3, t3));
            s = __fadd_rn(s, __fmul_rn(t4, t4));
            s = __fadd_rn(s, __fmul_rn(t5, t5));
            s = __fadd_rn(s, __fmul_rn(t6, t6));
            s = __fadd_rn(s, __fmul_rn(t7, t7));
            float D = __fsqrt_rn(s);
            if (need) {
                if (D < dval) { label = i; dval = D; }
                else          { dval = 0.0f; }
            }
        } else if (__all_sync(0xffffffffu, dval == 0.0f)) {
            break;
        }
    }

    g_labels[idx] = label;
    if (label >= 0) atomicAdd(&shist[label], 1);
    __syncthreads();
    if (t < NUM) g_blockhist[blockIdx.x * NUM + t] = shist[t];
}

// ------------------------------------------------------------------
// Per-cluster exclusive prefix over the 2048 block histograms, with the
// cross-cluster base scan fused into the last-arriving block (ticket).
__global__ void __launch_bounds__(128) scanKernel() {
    if (g_converged) return;
    __shared__ int wsum[4];
    __shared__ int sh[NUM];
    __shared__ int lastFlag;
    int cl   = blockIdx.x;
    int t    = threadIdx.x;             // 0..127
    int lane = t & 31, wid = t >> 5;
    const int PER = NBLK / 128;         // 16

    int v[PER];
    int s = 0;
    #pragma unroll
    for (int j = 0; j < PER; j++) {
        v[j] = g_blockhist[(t * PER + j) * NUM + cl];
        s += v[j];
    }

    int inc = s;
    #pragma unroll
    for (int o = 1; o < 32; o <<= 1) {
        int x = __shfl_up_sync(0xffffffffu, inc, o);
        if (lane >= o) inc += x;
    }
    if (lane == 31) wsum[wid] = inc;
    __syncthreads();
    int woff = 0;
    #pragma unroll
    for (int w = 0; w < 4; w++)
        if (w < wid) woff += wsum[w];

    if (t == 127) g_total[cl] = woff + inc;

    int run = woff + (inc - s);
    #pragma unroll
    for (int j = 0; j < PER; j++) {
        g_blockpre[(t * PER + j) * NUM + cl] = run;
        run += v[j];
    }

    // ---- fused base scan (last block via ticket) ----
    __threadfence();
    __syncthreads();
    if (t == 0) {
        int old = atomicAdd(&g_ticket1, 1);
        lastFlag = (old == NUM - 1);
    }
    __syncthreads();
    if (lastFlag) {
        int tv = g_total[t];
        sh[t] = tv;
        __syncthreads();
        #pragma unroll
        for (int o = 1; o < NUM; o <<= 1) {
            int x = (t >= o) ? sh[t - o] : 0;
            __syncthreads();
            sh[t] += x;
            __syncthreads();
        }
        g_base[t] = sh[t] - tv;
        if (t == 0) g_ticket1 = 0;
    }
}

// ------------------------------------------------------------------
// Stable scatter: point index -> g_idx, ascending index within each cluster.
__global__ void __launch_bounds__(256) scatterKernel() {
    if (g_converged) return;
    __shared__ int whist[8][NUM];
    int t    = threadIdx.x;
    int wid  = t >> 5;
    int lane = t & 31;

    #pragma unroll
    for (int j = t; j < 8 * NUM; j += 256) ((int*)whist)[j] = 0;
    __syncthreads();

    int idx = blockIdx.x * 256 + t;
    int lab = g_labels[idx];

    unsigned mask = __match_any_sync(0xffffffffu, lab);
    int rank   = __popc(mask & ((1u << lane) - 1u));
    int leader = __ffs(mask) - 1;
    if (lab >= 0 && lane == leader) whist[wid][lab] = __popc(mask);
    __syncthreads();

    if (t < NUM) {
        int run = 0;
        #pragma unroll
        for (int w = 0; w < 8; w++) {
            int v = whist[w][t];
            whist[w][t] = run;
            run += v;
        }
    }
    __syncthreads();

    if (lab >= 0) {
        int pos = g_base[lab] + g_blockpre[blockIdx.x * NUM + lab]
                + whist[wid][lab] + rank;
        g_idx[pos] = idx;
    }
}

// ------------------------------------------------------------------
// Exact ascending-order segment sums (tile-pipelined) FUSED with the
// per-cluster center update, count reset, last-block convergence check,
// and (on the final iteration) the output write:
//   - every block copies its 4096-label slice to out (shadow work)
//   - the ticket-last block writes the 1024 center floats (all updates
//     visible: each block fenced before its ticket arrival)
// Converged path still writes the (frozen) output.
__global__ void __launch_bounds__(TPB_SEG) segsumKernel(const float* __restrict__ data,
                                                        float* __restrict__ out,
                                                        int out_size, int writeOut) {
    __shared__ float buf[2][TILE][FD];     // 49152 B; tail phases reuse it
    int cl = blockIdx.x;
    int t  = threadIdx.x;
    int converged = g_converged;

    if (converged && !writeOut) return;

    if (!converged) {
        int start = g_base[cl];
        int n     = g_total[cl];
        int ntiles = (n + TILE - 1) / TILE;

        #define LOAD_TILE(g, s)                                              \
            do {                                                             \
                _Pragma("unroll")                                            \
                for (int h = 0; h < TILE / TPB_SEG; h++) {                   \
                    int p = (g) * TILE + h * TPB_SEG + t;                    \
                    if (p < n) {                                             \
                        int id = g_idx[start + p];                           \
                        float4 a = ((const float4*)data)[2 * id];            \
                        float4 b = ((const float4*)data)[2 * id + 1];        \
                        float* dst = buf[s][h * TPB_SEG + t];                \
                        ((float4*)dst)[0] = a;                               \
                        ((float4*)dst)[1] = b;                               \
                    }                                                        \
                }                                                            \
            } while (0)

        if (ntiles > 0) LOAD_TILE(0, 0);
        __syncthreads();

        float acc = 0.0f;
        for (int g = 0; g < ntiles; g++) {
            int s = g & 1;
            if (g + 1 < ntiles) LOAD_TILE(g + 1, s ^ 1);
            int m = min(n - g * TILE, TILE);
            if (t < FD) {
                #pragma unroll 16
                for (int k = 0; k < m; k++)
                    acc = __fadd_rn(acc, buf[s][k][t]);
            }
            __syncthreads();
        }
        #undef LOAD_TILE

        // ---- fused center update (fp ops identical to reference order) ----
        float* scr = &buf[0][0][0];
        if (t < FD) {
            float oldc = g_centers[cl * FD + t];
            float cntf = (float)n;
            float den  = fmaxf(cntf, 1.0f);
            float mval = __fdiv_rn(acc, den);
            float nc   = (cntf > 0.0f) ? mval : oldc;
            float d    = nc - oldc;
            g_centers[cl * FD + t] = nc;
            scr[t] = d;
        }
        if (t == 8) g_counts[cl] = 0;   // reset this cluster's gate accumulator
        __syncthreads();
        if (t == 0) {
            float dsq = 0.0f;
            #pragma unroll
            for (int k = 0; k < FD; k++)
                dsq = __fadd_rn(dsq, __fmul_rn(scr[k], scr[k]));
            g_dsq[cl] = dsq;
        }
    }

    // ---- output: labels slice (final iteration only; shadow work) ----
    if (writeOut) {
        int base = cl * SLICE_OUT;
        #pragma unroll
        for (int j = t; j < SLICE_OUT; j += TPB_SEG) {
            int idx = base + j;
            if (idx < out_size) out[idx] = (float)g_labels[idx];
        }
    }

    // ---- ticket: last block does convergence + (final) centers output ----
    __threadfence();
    __syncthreads();
    __shared__ int lastFlag;
    if (t == 0) {
        int old = atomicAdd(&g_ticket2, 1);
        lastFlag = (old == NUM - 1);
    }
    __syncthreads();
    if (lastFlag) {
        if (!converged) {
            float* red = &buf[1][0][0];
            if (t < NUM) red[t] = g_dsq[t];
            __syncthreads();
            #pragma unroll
            for (int s2 = 64; s2 > 0; s2 >>= 1) {
                if (t < s2) red[t] += red[t + s2];
                __syncthreads();
            }
            if (t == 0 && red[0] < THRESH2) g_converged = 1;
        }
        if (writeOut) {
            #pragma unroll
            for (int j = t; j < NUM * FD; j += TPB_SEG) {
                if (N_PTS + j < out_size)
                    out[N_PTS + j] = __ldcg(&g_centers[j]);
            }
        }
        if (t == 0) g_ticket2 = 0;
    }
}

// ------------------------------------------------------------------
extern "C" void kernel_launch(void* const* d_in, const int* in_sizes, int n_in,
                              void* d_out, int out_size) {
    const float* data    = (const float*)d_in[0];
    const float* centers = (const float*)d_in[1];
    float* out = (float*)d_out;

    // Y0 = largest f32 y with sqrt_rn(y) <= r, r = 0.32f.
    float  r  = 0.32f;
    double m  = 0.5 * ((double)r + (double)nextafterf(r, 2.0f));
    double m2 = m * m;
    float  Y0 = (float)m2;
    if ((double)Y0 >= m2) Y0 = nextafterf(Y0, 0.0f);

    // Fused init + pack + iteration-0 count
    countKernel0<<<NBLK, 256>>>(data, centers, Y0);
    for (int it = 0; it < MAXIT; it++) {
        assignKernel<<<NBLK, 256>>>(data, Y0);
        scanKernel<<<NUM, 128>>>();              // + fused base scan
        scatterKernel<<<NBLK, 256>>>();
        // + fused update/convergence/reset (+ output write on last iter)
        segsumKernel<<<NUM, TPB_SEG>>>(data, out, out_size,
                                       (it == MAXIT - 1) ? 1 : 0);
        if (it < MAXIT - 1) countKernel<<<NBLK, 256>>>(Y0);
    }
}

// round 15
// speedup vs baseline: 1.0386x; 1.0386x over previous
#include <cuda_runtime.h>
#include <math.h>

#define N_PTS   524288
#define FD      8
#define NUM     128
#define MAXIT   5
#define EPSF    1e-6f
#define THRESH2 1e-8f        /* (1e-4)^2 */
#define NBLK    (N_PTS / 256)   /* 2048 */
#define TPB_SEG 256
#define TILE    768             /* 2*768*8*4 = 49152 B static smem (max) */

// ---- f32x2 packed helpers (sm_100+; each half independently .rn-rounded) ----
__device__ __forceinline__ unsigned long long pack2f(float a, float b) {
    unsigned long long r;
    asm("mov.b64 %0, {%1, %2};" : "=l"(r)
        : "r"(__float_as_uint(a)), "r"(__float_as_uint(b)));
    return r;
}
__device__ __forceinline__ unsigned long long addx2(unsigned long long a,
                                                    unsigned long long b) {
    unsigned long long r;
    asm("add.rn.f32x2 %0, %1, %2;" : "=l"(r) : "l"(a), "l"(b));
    return r;
}
__device__ __forceinline__ unsigned long long mulx2(unsigned long long a,
                                                    unsigned long long b) {
    unsigned long long r;
    asm("mul.rn.f32x2 %0, %1, %2;" : "=l"(r) : "l"(a), "l"(b));
    return r;
}
__device__ __forceinline__ void unpack2f(float& lo, float& hi, unsigned long long v) {
    unsigned x, y;
    asm("mov.b64 {%0, %1}, %2;" : "=r"(x), "=r"(y) : "l"(v));
    lo = __uint_as_float(x); hi = __uint_as_float(y);
}

// ---- device scratch (no allocations allowed) ----
__device__ float  g_centers[NUM * FD];
__device__ int    g_counts[NUM];     // zero at entry: zero-init + segsum resets
__device__ float  g_dsq[NUM];
__device__ int    g_labels[N_PTS];
__device__ int    g_converged;
__device__ int    g_ticket1;
__device__ int    g_ticket2;
__device__ __align__(16) float2 g_xy[N_PTS];  // packed first-2 coords (4 MB)
// counting-sort scratch
__device__ int    g_blockhist[NBLK * NUM];
__device__ int    g_blockpre[NBLK * NUM];
__device__ int    g_base[NUM];
__device__ int    g_total[NUM];
__device__ int    g_idx[N_PTS];

// ------------------------------------------------------------------
// Iteration-0 fused kernel: init globals (block 0) + pack xy coords +
// in-radius counts for the INITIAL centers (read directly from input —
// same values g_centers would hold). Gate arithmetic bit-identical:
// sp2 = rn(rn(dx*dx)+rn(dy*dy)), dx = rn(x + (-cx)); sp2 <= Y0.
__global__ void __launch_bounds__(256) countKernel0(const float* __restrict__ data,
                                                    const float* __restrict__ centers_in,
                                                    float Y0) {
    __shared__ unsigned long long ncx2[NUM / 2];
    __shared__ unsigned long long ncy2[NUM / 2];
    __shared__ int scnt[NUM];
    int t = threadIdx.x;

    if (blockIdx.x == 0) {               // fused init (visible at kernel boundary)
        #pragma unroll
        for (int j = t; j < NUM * FD; j += 256) g_centers[j] = centers_in[j];
        if (t == 0) { g_converged = 0; g_ticket1 = 0; g_ticket2 = 0; }
    }
    if (t < NUM / 2) {
        float cx0 = centers_in[(2 * t)     * FD];
        float cy0 = centers_in[(2 * t)     * FD + 1];
        float cx1 = centers_in[(2 * t + 1) * FD];
        float cy1 = centers_in[(2 * t + 1) * FD + 1];
        ncx2[t] = pack2f(-cx0, -cx1);
        ncy2[t] = pack2f(-cy0, -cy1);
    }
    if (t < NUM) scnt[t] = 0;
    __syncthreads();

    int idx  = blockIdx.x * 256 + t;
    float2 p = *(const float2*)(data + (size_t)idx * FD);
    g_xy[idx] = p;                       // fused pack
    unsigned long long pxx = pack2f(p.x, p.x);
    unsigned long long pyy = pack2f(p.y, p.y);
    int lane = t & 31;

    int c0 = 0, c1 = 0, c2 = 0, c3 = 0;
    #pragma unroll 4
    for (int ii = 0; ii < 32; ii++) {
        bool mine = (lane == ii);
        #pragma unroll
        for (int q = 0; q < 2; q++) {
            int pr = q * 32 + ii;
            unsigned long long dxv = addx2(pxx, ncx2[pr]);
            unsigned long long dyv = addx2(pyy, ncy2[pr]);
            unsigned long long sp2v = addx2(mulx2(dxv, dxv), mulx2(dyv, dyv));
            float slo, shi;
            unpack2f(slo, shi, sp2v);
            unsigned m0 = __ballot_sync(0xffffffffu, slo <= Y0);
            unsigned m1 = __ballot_sync(0xffffffffu, shi <= Y0);
            int p0 = __popc(m0), p1 = __popc(m1);
            if (mine) {
                if (q == 0) { c0 += p0; c1 += p1; }
                else        { c2 += p0; c3 += p1; }
            }
        }
    }
    atomicAdd(&scnt[2 * lane],      c0);
    atomicAdd(&scnt[2 * lane + 1],  c1);
    atomicAdd(&scnt[64 + 2 * lane], c2);
    atomicAdd(&scnt[65 + 2 * lane], c3);
    __syncthreads();
    if (t < NUM) atomicAdd(&g_counts[t], scnt[t]);
}

// ------------------------------------------------------------------
// Per-center in-radius counts for iterations 1+ (reads updated g_centers
// and packed g_xy). Identical gate arithmetic.
__global__ void __launch_bounds__(256) countKernel(float Y0) {
    if (g_converged) return;
    __shared__ unsigned long long ncx2[NUM / 2];
    __shared__ unsigned long long ncy2[NUM / 2];
    __shared__ int scnt[NUM];
    int t = threadIdx.x;
    if (t < NUM / 2) {
        float cx0 = g_centers[(2 * t)     * FD];
        float cy0 = g_centers[(2 * t)     * FD + 1];
        float cx1 = g_centers[(2 * t + 1) * FD];
        float cy1 = g_centers[(2 * t + 1) * FD + 1];
        ncx2[t] = pack2f(-cx0, -cx1);
        ncy2[t] = pack2f(-cy0, -cy1);
    }
    if (t < NUM) scnt[t] = 0;
    __syncthreads();

    int idx  = blockIdx.x * 256 + t;
    float2 p = g_xy[idx];
    unsigned long long pxx = pack2f(p.x, p.x);
    unsigned long long pyy = pack2f(p.y, p.y);
    int lane = t & 31;

    int c0 = 0, c1 = 0, c2 = 0, c3 = 0;
    #pragma unroll 4
    for (int ii = 0; ii < 32; ii++) {
        bool mine = (lane == ii);
        #pragma unroll
        for (int q = 0; q < 2; q++) {
            int pr = q * 32 + ii;
            unsigned long long dxv = addx2(pxx, ncx2[pr]);
            unsigned long long dyv = addx2(pyy, ncy2[pr]);
            unsigned long long sp2v = addx2(mulx2(dxv, dxv), mulx2(dyv, dyv));
            float slo, shi;
            unpack2f(slo, shi, sp2v);
            unsigned m0 = __ballot_sync(0xffffffffu, slo <= Y0);
            unsigned m1 = __ballot_sync(0xffffffffu, shi <= Y0);
            int p0 = __popc(m0), p1 = __popc(m1);
            if (mine) {
                if (q == 0) { c0 += p0; c1 += p1; }
                else        { c2 += p0; c3 += p1; }
            }
        }
    }
    atomicAdd(&scnt[2 * lane],      c0);
    atomicAdd(&scnt[2 * lane + 1],  c1);
    atomicAdd(&scnt[64 + 2 * lane], c2);
    atomicAdd(&scnt[65 + 2 * lane], c3);
    __syncthreads();
    if (t < NUM) atomicAdd(&g_counts[t], scnt[t]);
}

// ------------------------------------------------------------------
// Assignment: faithful reference fp arithmetic (proven round-9/11 form:
// sqrt-space compare; FSQRT rides the idle MUFU pipe for free).
__global__ void __launch_bounds__(256) assignKernel(const float* __restrict__ data,
                                                    float Y0) {
    if (g_converged) return;
    __shared__ float4 sc[NUM * 2];
    __shared__ int    shist[NUM];
    int t = threadIdx.x;

    {   // centers with "enough" gate baked into coord 0
        float4 v = ((const float4*)g_centers)[t];
        if ((t & 1) == 0) {
            if (g_counts[t >> 1] <= 1) v.x += 1e9f;
        }
        sc[t] = v;
    }
    if (t < NUM) shist[t] = 0;
    __syncthreads();

    int idx = blockIdx.x * 256 + t;
    float4 p0 = ((const float4*)data)[2 * idx];
    float4 p1 = ((const float4*)data)[2 * idx + 1];

    float dval = 1000.0f;
    int   label = -1;

    for (int i = 0; i < NUM; i++) {
        float4 c0 = sc[2 * i];
        float dx0 = p0.x - c0.x;
        float dx1 = p0.y - c0.y;
        float sp2 = __fadd_rn(__fmul_rn(dx0, dx0), __fmul_rn(dx1, dx1));
        bool need = (sp2 <= Y0) && (dval > 0.0f);
        if (__any_sync(0xffffffffu, need)) {
            float4 c1 = sc[2 * i + 1];
            float t0 = __fadd_rn(dx0, EPSF);
            float t1 = __fadd_rn(dx1, EPSF);
            float t2 = __fadd_rn(p0.z - c0.z, EPSF);
            float t3 = __fadd_rn(p0.w - c0.w, EPSF);
            float t4 = __fadd_rn(p1.x - c1.x, EPSF);
            float t5 = __fadd_rn(p1.y - c1.y, EPSF);
            float t6 = __fadd_rn(p1.z - c1.z, EPSF);
            float t7 = __fadd_rn(p1.w - c1.w, EPSF);
            float s = __fmul_rn(t0, t0);
            s = __fadd_rn(s, __fmul_rn(t1, t1));
            s = __fadd_rn(s, __fmul_rn(t2, t2));
            s = __fadd_rn(s, __fmul_rn(t3, t3));
            s = __fadd_rn(s, __fmul_rn(t4, t4));
            s = __fadd_rn(s, __fmul_rn(t5, t5));
            s = __fadd_rn(s, __fmul_rn(t6, t6));
            s = __fadd_rn(s, __fmul_rn(t7, t7));
            float D = __fsqrt_rn(s);
            if (need) {
                if (D < dval) { label = i; dval = D; }
                else          { dval = 0.0f; }
            }
        } else if (__all_sync(0xffffffffu, dval == 0.0f)) {
            break;
        }
    }

    g_labels[idx] = label;
    if (label >= 0) atomicAdd(&shist[label], 1);
    __syncthreads();
    if (t < NUM) g_blockhist[blockIdx.x * NUM + t] = shist[t];
}

// ------------------------------------------------------------------
// Per-cluster exclusive prefix over the 2048 block histograms, with the
// cross-cluster base scan fused into the last-arriving block (ticket).
__global__ void __launch_bounds__(128) scanKernel() {
    if (g_converged) return;
    __shared__ int wsum[4];
    __shared__ int sh[NUM];
    __shared__ int lastFlag;
    int cl   = blockIdx.x;
    int t    = threadIdx.x;             // 0..127
    int lane = t & 31, wid = t >> 5;
    const int PER = NBLK / 128;         // 16

    int v[PER];
    int s = 0;
    #pragma unroll
    for (int j = 0; j < PER; j++) {
        v[j] = g_blockhist[(t * PER + j) * NUM + cl];
        s += v[j];
    }

    int inc = s;
    #pragma unroll
    for (int o = 1; o < 32; o <<= 1) {
        int x = __shfl_up_sync(0xffffffffu, inc, o);
        if (lane >= o) inc += x;
    }
    if (lane == 31) wsum[wid] = inc;
    __syncthreads();
    int woff = 0;
    #pragma unroll
    for (int w = 0; w < 4; w++)
        if (w < wid) woff += wsum[w];

    if (t == 127) g_total[cl] = woff + inc;

    int run = woff + (inc - s);
    #pragma unroll
    for (int j = 0; j < PER; j++) {
        g_blockpre[(t * PER + j) * NUM + cl] = run;
        run += v[j];
    }

    // ---- fused base scan (last block via ticket) ----
    __threadfence();
    __syncthreads();
    if (t == 0) {
        int old = atomicAdd(&g_ticket1, 1);
        lastFlag = (old == NUM - 1);
    }
    __syncthreads();
    if (lastFlag) {
        int tv = g_total[t];
        sh[t] = tv;
        __syncthreads();
        #pragma unroll
        for (int o = 1; o < NUM; o <<= 1) {
            int x = (t >= o) ? sh[t - o] : 0;
            __syncthreads();
            sh[t] += x;
            __syncthreads();
        }
        g_base[t] = sh[t] - tv;
        if (t == 0) g_ticket1 = 0;
    }
}

// ------------------------------------------------------------------
// Stable scatter: point index -> g_idx, ascending index within each cluster.
__global__ void __launch_bounds__(256) scatterKernel() {
    if (g_converged) return;
    __shared__ int whist[8][NUM];
    int t    = threadIdx.x;
    int wid  = t >> 5;
    int lane = t & 31;

    #pragma unroll
    for (int j = t; j < 8 * NUM; j += 256) ((int*)whist)[j] = 0;
    __syncthreads();

    int idx = blockIdx.x * 256 + t;
    int lab = g_labels[idx];

    unsigned mask = __match_any_sync(0xffffffffu, lab);
    int rank   = __popc(mask & ((1u << lane) - 1u));
    int leader = __ffs(mask) - 1;
    if (lab >= 0 && lane == leader) whist[wid][lab] = __popc(mask);
    __syncthreads();

    if (t < NUM) {
        int run = 0;
        #pragma unroll
        for (int w = 0; w < 8; w++) {
            int v = whist[w][t];
            whist[w][t] = run;
            run += v;
        }
    }
    __syncthreads();

    if (lab >= 0) {
        int pos = g_base[lab] + g_blockpre[blockIdx.x * NUM + lab]
                + whist[wid][lab] + rank;
        g_idx[pos] = idx;
    }
}

// ------------------------------------------------------------------
// Exact ascending-order segment sums (tile-pipelined) FUSED with the
// per-cluster center update, the per-cluster count reset, and the
// last-block convergence check (ticket).
__global__ void __launch_bounds__(TPB_SEG) segsumKernel(const float* __restrict__ data) {
    if (g_converged) return;
    __shared__ float buf[2][TILE][FD];     // 49152 B; tail phases reuse it
    int cl = blockIdx.x;
    int t  = threadIdx.x;
    int start = g_base[cl];
    int n     = g_total[cl];
    int ntiles = (n + TILE - 1) / TILE;

    #define LOAD_TILE(g, s)                                              \
        do {                                                             \
            _Pragma("unroll")                                            \
            for (int h = 0; h < TILE / TPB_SEG; h++) {                   \
                int p = (g) * TILE + h * TPB_SEG + t;                    \
                if (p < n) {                                             \
                    int id = g_idx[start + p];                           \
                    float4 a = ((const float4*)data)[2 * id];            \
                    float4 b = ((const float4*)data)[2 * id + 1];        \
                    float* dst = buf[s][h * TPB_SEG + t];                \
                    ((float4*)dst)[0] = a;                               \
                    ((float4*)dst)[1] = b;                               \
                }                                                        \
            }                                                            \
        } while (0)

    if (ntiles > 0) LOAD_TILE(0, 0);
    __syncthreads();

    float acc = 0.0f;
    for (int g = 0; g < ntiles; g++) {
        int s = g & 1;
        if (g + 1 < ntiles) LOAD_TILE(g + 1, s ^ 1);
        int m = min(n - g * TILE, TILE);
        if (t < FD) {
            #pragma unroll 16
            for (int k = 0; k < m; k++)
                acc = __fadd_rn(acc, buf[s][k][t]);
        }
        __syncthreads();
    }
    #undef LOAD_TILE

    // ---- fused center update (fp ops identical to reference order) ----
    float* scr = &buf[0][0][0];
    if (t < FD) {
        float oldc = g_centers[cl * FD + t];
        float cntf = (float)n;
        float den  = fmaxf(cntf, 1.0f);
        float mval = __fdiv_rn(acc, den);
        float nc   = (cntf > 0.0f) ? mval : oldc;
        float d    = nc - oldc;
        g_centers[cl * FD + t] = nc;
        scr[t] = d;
    }
    if (t == 8) g_counts[cl] = 0;   // reset this cluster's gate accumulator
    __syncthreads();
    if (t == 0) {
        float dsq = 0.0f;
        #pragma unroll
        for (int k = 0; k < FD; k++)
            dsq = __fadd_rn(dsq, __fmul_rn(scr[k], scr[k]));
        g_dsq[cl] = dsq;
    }

    // ---- convergence (last block via ticket, exact tree order) ----
    __threadfence();
    __syncthreads();
    int* iscr = (int*)scr;
    if (t == 0) {
        int old = atomicAdd(&g_ticket2, 1);
        iscr[16] = (old == NUM - 1);
    }
    __syncthreads();
    if (iscr[16]) {
        float* red = scr + 64;
        if (t < NUM) red[t] = g_dsq[t];
        __syncthreads();
        #pragma unroll
        for (int s2 = 64; s2 > 0; s2 >>= 1) {
            if (t < s2) red[t] += red[t + s2];
            __syncthreads();
        }
        if (t == 0) {
            if (red[0] < THRESH2) g_converged = 1;
            g_ticket2 = 0;
        }
    }
}

// ------------------------------------------------------------------
// Output: [ labels as float (N) | centers (NUM*FD) ], float32
__global__ void __launch_bounds__(256) outputKernel(float* __restrict__ out, int out_size) {
    int idx = blockIdx.x * 256 + threadIdx.x;
    if (idx < N_PTS && idx < out_size)
        out[idx] = (float)g_labels[idx];
    if (idx < NUM * FD && (N_PTS + idx) < out_size)
        out[N_PTS + idx] = g_centers[idx];
}

// ------------------------------------------------------------------
extern "C" void kernel_launch(void* const* d_in, const int* in_sizes, int n_in,
                              void* d_out, int out_size) {
    const float* data    = (const float*)d_in[0];
    const float* centers = (const float*)d_in[1];

    // Y0 = largest f32 y with sqrt_rn(y) <= r, r = 0.32f.
    float  r  = 0.32f;
    double m  = 0.5 * ((double)r + (double)nextafterf(r, 2.0f));
    double m2 = m * m;
    float  Y0 = (float)m2;
    if ((double)Y0 >= m2) Y0 = nextafterf(Y0, 0.0f);

    // Fused init + pack + iteration-0 count
    countKernel0<<<NBLK, 256>>>(data, centers, Y0);
    for (int it = 0; it < MAXIT; it++) {
        assignKernel<<<NBLK, 256>>>(data, Y0);
        scanKernel<<<NUM, 128>>>();              // + fused base scan
        scatterKernel<<<NBLK, 256>>>();
        segsumKernel<<<NUM, TPB_SEG>>>(data);    // + fused update/convergence/reset
        if (it < MAXIT - 1) countKernel<<<NBLK, 256>>>(Y0);
    }
    outputKernel<<<NBLK, 256>>>((float*)d_out, out_size);
}

// round 17
// speedup vs baseline: 1.0442x; 1.0054x over previous
#include <cuda_runtime.h>
#include <math.h>

#define N_PTS   524288
#define FD      8
#define NUM     128
#define MAXIT   5
#define EPSF    1e-6f
#define THRESH2 1e-8f        /* (1e-4)^2 */
#define NBLK    (N_PTS / 256)   /* 2048 */
#define TPB_SEG 256
#define TILE    768             /* 2*768*8*4 = 49152 B static smem (max) */
#define NCELL   4096             /* 64x64 spatial grid */

// ---- f32x2 packed helpers (sm_100+; each half independently .rn-rounded) ----
__device__ __forceinline__ unsigned long long pack2f(float a, float b) {
    unsigned long long r;
    asm("mov.b64 %0, {%1, %2};" : "=l"(r)
        : "r"(__float_as_uint(a)), "r"(__float_as_uint(b)));
    return r;
}
__device__ __forceinline__ unsigned long long addx2(unsigned long long a,
                                                    unsigned long long b) {
    unsigned long long r;
    asm("add.rn.f32x2 %0, %1, %2;" : "=l"(r) : "l"(a), "l"(b));
    return r;
}
__device__ __forceinline__ unsigned long long mulx2(unsigned long long a,
                                                    unsigned long long b) {
    unsigned long long r;
    asm("mul.rn.f32x2 %0, %1, %2;" : "=l"(r) : "l"(a), "l"(b));
    return r;
}
__device__ __forceinline__ void unpack2f(float& lo, float& hi, unsigned long long v) {
    unsigned x, y;
    asm("mov.b64 {%0, %1}, %2;" : "=r"(x), "=r"(y) : "l"(v));
    lo = __uint_as_float(x); hi = __uint_as_float(y);
}

// ---- device scratch (no allocations allowed) ----
__device__ float  g_centers[NUM * FD];
__device__ int    g_counts[NUM];     // zero at entry: zero-init + segsum resets
__device__ float  g_dsq[NUM];
__device__ int    g_labels[N_PTS];
__device__ int    g_converged;
__device__ int    g_ticket1;
__device__ int    g_ticket2;
__device__ __align__(16) float2 g_xy[N_PTS];  // packed first-2 coords (4 MB)
// spatial-coherence ordering (one-time)
__device__ int    g_cellcnt[NCELL];  // zero at entry (zero-init + cellScan resets)
__device__ int    g_cellcur[NCELL];
__device__ int    g_order[N_PTS];
// counting-sort scratch
__device__ int    g_blockhist[NBLK * NUM];  // zero at entry (zero-init + scan resets)
__device__ int    g_blockpre[NBLK * NUM];
__device__ int    g_base[NUM];
__device__ int    g_total[NUM];
__device__ int    g_idx[N_PTS];

__device__ __forceinline__ int cell_of(float2 p) {
    int cx = min((int)(p.x * 64.0f), 63);
    int cy = min((int)(p.y * 64.0f), 63);
    return cy * 64 + cx;
}

// ------------------------------------------------------------------
// Iteration-0 fused kernel: init globals (block 0) + pack xy coords +
// in-radius counts for the INITIAL centers + spatial cell histogram.
// Gate arithmetic bit-identical:
// sp2 = rn(rn(dx*dx)+rn(dy*dy)), dx = rn(x + (-cx)); sp2 <= Y0.
__global__ void __launch_bounds__(256) countKernel0(const float* __restrict__ data,
                                                    const float* __restrict__ centers_in,
                                                    float Y0) {
    __shared__ unsigned long long ncx2[NUM / 2];
    __shared__ unsigned long long ncy2[NUM / 2];
    __shared__ int scnt[NUM];
    int t = threadIdx.x;

    if (blockIdx.x == 0) {               // fused init (visible at kernel boundary)
        #pragma unroll
        for (int j = t; j < NUM * FD; j += 256) g_centers[j] = centers_in[j];
        if (t == 0) { g_converged = 0; g_ticket1 = 0; g_ticket2 = 0; }
    }
    if (t < NUM / 2) {
        float cx0 = centers_in[(2 * t)     * FD];
        float cy0 = centers_in[(2 * t)     * FD + 1];
        float cx1 = centers_in[(2 * t + 1) * FD];
        float cy1 = centers_in[(2 * t + 1) * FD + 1];
        ncx2[t] = pack2f(-cx0, -cx1);
        ncy2[t] = pack2f(-cy0, -cy1);
    }
    if (t < NUM) scnt[t] = 0;
    __syncthreads();

    int idx  = blockIdx.x * 256 + t;
    float2 p = *(const float2*)(data + (size_t)idx * FD);
    g_xy[idx] = p;                       // fused pack
    atomicAdd(&g_cellcnt[cell_of(p)], 1);  // fused spatial histogram
    unsigned long long pxx = pack2f(p.x, p.x);
    unsigned long long pyy = pack2f(p.y, p.y);
    int lane = t & 31;

    int c0 = 0, c1 = 0, c2 = 0, c3 = 0;
    #pragma unroll 4
    for (int ii = 0; ii < 32; ii++) {
        bool mine = (lane == ii);
        #pragma unroll
        for (int q = 0; q < 2; q++) {
            int pr = q * 32 + ii;
            unsigned long long dxv = addx2(pxx, ncx2[pr]);
            unsigned long long dyv = addx2(pyy, ncy2[pr]);
            unsigned long long sp2v = addx2(mulx2(dxv, dxv), mulx2(dyv, dyv));
            float slo, shi;
            unpack2f(slo, shi, sp2v);
            unsigned m0 = __ballot_sync(0xffffffffu, slo <= Y0);
            unsigned m1 = __ballot_sync(0xffffffffu, shi <= Y0);
            int p0 = __popc(m0), p1 = __popc(m1);
            if (mine) {
                if (q == 0) { c0 += p0; c1 += p1; }
                else        { c2 += p0; c3 += p1; }
            }
        }
    }
    atomicAdd(&scnt[2 * lane],      c0);
    atomicAdd(&scnt[2 * lane + 1],  c1);
    atomicAdd(&scnt[64 + 2 * lane], c2);
    atomicAdd(&scnt[65 + 2 * lane], c3);
    __syncthreads();
    if (t < NUM) atomicAdd(&g_counts[t], scnt[t]);
}

// ------------------------------------------------------------------
// One-time: exclusive scan of cell counts -> atomic cursors; zeroes
// g_cellcnt after reading (restores the zero-at-entry invariant for
// the next harness replay).
__global__ void __launch_bounds__(1024) cellScanKernel() {
    __shared__ int wsum[32];
    int t = threadIdx.x;
    int lane = t & 31, wid = t >> 5;
    int v[4]; int s = 0;
    #pragma unroll
    for (int j = 0; j < 4; j++) {
        v[j] = g_cellcnt[t * 4 + j];
        g_cellcnt[t * 4 + j] = 0;
        s += v[j];
    }
    int inc = s;
    #pragma unroll
    for (int o = 1; o < 32; o <<= 1) {
        int x = __shfl_up_sync(0xffffffffu, inc, o);
        if (lane >= o) inc += x;
    }
    if (lane == 31) wsum[wid] = inc;
    __syncthreads();
    if (wid == 0) {
        int w = wsum[lane];
        int winc = w;
        #pragma unroll
        for (int o = 1; o < 32; o <<= 1) {
            int x = __shfl_up_sync(0xffffffffu, winc, o);
            if (lane >= o) winc += x;
        }
        wsum[lane] = winc - w;      // exclusive warp offsets
    }
    __syncthreads();
    int base = wsum[wid] + (inc - s);
    #pragma unroll
    for (int j = 0; j < 4; j++) {
        g_cellcur[t * 4 + j] = base;
        base += v[j];
    }
}

// One-time: scatter point indices into cell-sorted order.
// Within-cell order is nondeterministic (atomic) but output-invariant:
// per-point label results are independent of warp grouping.
__global__ void __launch_bounds__(256) cellScatterKernel() {
    int idx = blockIdx.x * 256 + threadIdx.x;
    int pos = atomicAdd(&g_cellcur[cell_of(g_xy[idx])], 1);
    g_order[pos] = idx;
}

// ------------------------------------------------------------------
// Per-center in-radius counts for iterations 1+ (identical arithmetic).
__global__ void __launch_bounds__(256) countKernel(float Y0) {
    if (g_converged) return;
    __shared__ unsigned long long ncx2[NUM / 2];
    __shared__ unsigned long long ncy2[NUM / 2];
    __shared__ int scnt[NUM];
    int t = threadIdx.x;
    if (t < NUM / 2) {
        float cx0 = g_centers[(2 * t)     * FD];
        float cy0 = g_centers[(2 * t)     * FD + 1];
        float cx1 = g_centers[(2 * t + 1) * FD];
        float cy1 = g_centers[(2 * t + 1) * FD + 1];
        ncx2[t] = pack2f(-cx0, -cx1);
        ncy2[t] = pack2f(-cy0, -cy1);
    }
    if (t < NUM) scnt[t] = 0;
    __syncthreads();

    int idx  = blockIdx.x * 256 + t;
    float2 p = g_xy[idx];
    unsigned long long pxx = pack2f(p.x, p.x);
    unsigned long long pyy = pack2f(p.y, p.y);
    int lane = t & 31;

    int c0 = 0, c1 = 0, c2 = 0, c3 = 0;
    #pragma unroll 4
    for (int ii = 0; ii < 32; ii++) {
        bool mine = (lane == ii);
        #pragma unroll
        for (int q = 0; q < 2; q++) {
            int pr = q * 32 + ii;
            unsigned long long dxv = addx2(pxx, ncx2[pr]);
            unsigned long long dyv = addx2(pyy, ncy2[pr]);
            unsigned long long sp2v = addx2(mulx2(dxv, dxv), mulx2(dyv, dyv));
            float slo, shi;
            unpack2f(slo, shi, sp2v);
            unsigned m0 = __ballot_sync(0xffffffffu, slo <= Y0);
            unsigned m1 = __ballot_sync(0xffffffffu, shi <= Y0);
            int p0 = __popc(m0), p1 = __popc(m1);
            if (mine) {
                if (q == 0) { c0 += p0; c1 += p1; }
                else        { c2 += p0; c3 += p1; }
            }
        }
    }
    atomicAdd(&scnt[2 * lane],      c0);
    atomicAdd(&scnt[2 * lane + 1],  c1);
    atomicAdd(&scnt[64 + 2 * lane], c2);
    atomicAdd(&scnt[65 + 2 * lane], c3);
    __syncthreads();
    if (t < NUM) atomicAdd(&g_counts[t], scnt[t]);
}

// ------------------------------------------------------------------
// Assignment over SPATIALLY SORTED point order: identical per-point fp
// arithmetic and decisions; warps now exit the center loop much earlier
// because all 32 lanes poison at nearly the same center index.
// Histogram goes to the point's ORIGINAL block (stable-sort requirement)
// via spread global atomics. g_blockhist is zero at entry (scan resets).
__global__ void __launch_bounds__(256) assignKernel(const float* __restrict__ data,
                                                    float Y0) {
    if (g_converged) return;
    __shared__ float4 sc[NUM * 2];
    int t = threadIdx.x;

    {   // centers with "enough" gate baked into coord 0
        float4 v = ((const float4*)g_centers)[t];
        if ((t & 1) == 0) {
            if (g_counts[t >> 1] <= 1) v.x += 1e9f;
        }
        sc[t] = v;
    }
    __syncthreads();

    int id = g_order[blockIdx.x * 256 + t];
    float4 p0 = __ldg(&((const float4*)data)[2 * id]);
    float4 p1 = __ldg(&((const float4*)data)[2 * id + 1]);

    float dval = 1000.0f;
    int   label = -1;

    for (int i = 0; i < NUM; i++) {
        float4 c0 = sc[2 * i];
        float dx0 = p0.x - c0.x;
        float dx1 = p0.y - c0.y;
        float sp2 = __fadd_rn(__fmul_rn(dx0, dx0), __fmul_rn(dx1, dx1));
        bool need = (sp2 <= Y0) && (dval > 0.0f);
        if (__any_sync(0xffffffffu, need)) {
            float4 c1 = sc[2 * i + 1];
            float t0 = __fadd_rn(dx0, EPSF);
            float t1 = __fadd_rn(dx1, EPSF);
            float t2 = __fadd_rn(p0.z - c0.z, EPSF);
            float t3 = __fadd_rn(p0.w - c0.w, EPSF);
            float t4 = __fadd_rn(p1.x - c1.x, EPSF);
            float t5 = __fadd_rn(p1.y - c1.y, EPSF);
            float t6 = __fadd_rn(p1.z - c1.z, EPSF);
            float t7 = __fadd_rn(p1.w - c1.w, EPSF);
            float s = __fmul_rn(t0, t0);
            s = __fadd_rn(s, __fmul_rn(t1, t1));
            s = __fadd_rn(s, __fmul_rn(t2, t2));
            s = __fadd_rn(s, __fmul_rn(t3, t3));
            s = __fadd_rn(s, __fmul_rn(t4, t4));
            s = __fadd_rn(s, __fmul_rn(t5, t5));
            s = __fadd_rn(s, __fmul_rn(t6, t6));
            s = __fadd_rn(s, __fmul_rn(t7, t7));
            float D = __fsqrt_rn(s);
            if (need) {
                if (D < dval) { label = i; dval = D; }
                else          { dval = 0.0f; }
            }
        } else if (__all_sync(0xffffffffu, dval == 0.0f)) {
            break;
        }
    }

    g_labels[id] = label;
    if (label >= 0)
        atomicAdd(&g_blockhist[(id >> 8) * NUM + label], 1);
}

// ------------------------------------------------------------------
// Per-cluster exclusive prefix over the 2048 block histograms, with the
// cross-cluster base scan fused into the last-arriving block (ticket).
// Zeroes g_blockhist after reading (invariant for next assign).
__global__ void __launch_bounds__(128) scanKernel() {
    if (g_converged) return;
    __shared__ int wsum[4];
    __shared__ int sh[NUM];
    __shared__ int lastFlag;
    int cl   = blockIdx.x;
    int t    = threadIdx.x;             // 0..127
    int lane = t & 31, wid = t >> 5;
    const int PER = NBLK / 128;         // 16

    int v[PER];
    int s = 0;
    #pragma unroll
    for (int j = 0; j < PER; j++) {
        int o = (t * PER + j) * NUM + cl;
        v[j] = g_blockhist[o];
        g_blockhist[o] = 0;
        s += v[j];
    }

    int inc = s;
    #pragma unroll
    for (int o = 1; o < 32; o <<= 1) {
        int x = __shfl_up_sync(0xffffffffu, inc, o);
        if (lane >= o) inc += x;
    }
    if (lane == 31) wsum[wid] = inc;
    __syncthreads();
    int woff = 0;
    #pragma unroll
    for (int w = 0; w < 4; w++)
        if (w < wid) woff += wsum[w];

    if (t == 127) g_total[cl] = woff + inc;

    int run = woff + (inc - s);
    #pragma unroll
    for (int j = 0; j < PER; j++) {
        g_blockpre[(t * PER + j) * NUM + cl] = run;
        run += v[j];
    }

    // ---- fused base scan (last block via ticket) ----
    __threadfence();
    __syncthreads();
    if (t == 0) {
        int old = atomicAdd(&g_ticket1, 1);
        lastFlag = (old == NUM - 1);
    }
    __syncthreads();
    if (lastFlag) {
        int tv = g_total[t];
        sh[t] = tv;
        __syncthreads();
        #pragma unroll
        for (int o = 1; o < NUM; o <<= 1) {
            int x = (t >= o) ? sh[t - o] : 0;
            __syncthreads();
            sh[t] += x;
            __syncthreads();
        }
        g_base[t] = sh[t] - tv;
        if (t == 0) g_ticket1 = 0;
    }
}

// ------------------------------------------------------------------
// Stable scatter: point index -> g_idx, ascending index within each cluster.
__global__ void __launch_bounds__(256) scatterKernel() {
    if (g_converged) return;
    __shared__ int whist[8][NUM];
    int t    = threadIdx.x;
    int wid  = t >> 5;
    int lane = t & 31;

    #pragma unroll
    for (int j = t; j < 8 * NUM; j += 256) ((int*)whist)[j] = 0;
    __syncthreads();

    int idx = blockIdx.x * 256 + t;
    int lab = g_labels[idx];

    unsigned mask = __match_any_sync(0xffffffffu, lab);
    int rank   = __popc(mask & ((1u << lane) - 1u));
    int leader = __ffs(mask) - 1;
    if (lab >= 0 && lane == leader) whist[wid][lab] = __popc(mask);
    __syncthreads();

    if (t < NUM) {
        int run = 0;
        #pragma unroll
        for (int w = 0; w < 8; w++) {
            int v = whist[w][t];
            whist[w][t] = run;
            run += v;
        }
    }
    __syncthreads();

    if (lab >= 0) {
        int pos = g_base[lab] + g_blockpre[blockIdx.x * NUM + lab]
                + whist[wid][lab] + rank;
        g_idx[pos] = idx;
    }
}

// ------------------------------------------------------------------
// Exact ascending-order segment sums (tile-pipelined) FUSED with the
// per-cluster center update, the per-cluster count reset, and the
// last-block convergence check (ticket).
__global__ void __launch_bounds__(TPB_SEG) segsumKernel(const float* __restrict__ data) {
    if (g_converged) return;
    __shared__ float buf[2][TILE][FD];     // 49152 B; tail phases reuse it
    int cl = blockIdx.x;
    int t  = threadIdx.x;
    int start = g_base[cl];
    int n     = g_total[cl];
    int ntiles = (n + TILE - 1) / TILE;

    #define LOAD_TILE(g, s)                                              \
        do {                                                             \
            _Pragma("unroll")                                            \
            for (int h = 0; h < TILE / TPB_SEG; h++) {                   \
                int p = (g) * TILE + h * TPB_SEG + t;                    \
                if (p < n) {                                             \
                    int id = g_idx[start + p];                           \
                    float4 a = ((const float4*)data)[2 * id];            \
                    float4 b = ((const float4*)data)[2 * id + 1];        \
                    float* dst = buf[s][h * TPB_SEG + t];                \
                    ((float4*)dst)[0] = a;                               \
                    ((float4*)dst)[1] = b;                               \
                }                                                        \
            }                                                            \
        } while (0)

    if (ntiles > 0) LOAD_TILE(0, 0);
    __syncthreads();

    float acc = 0.0f;
    for (int g = 0; g < ntiles; g++) {
        int s = g & 1;
        if (g + 1 < ntiles) LOAD_TILE(g + 1, s ^ 1);
        int m = min(n - g * TILE, TILE);
        if (t < FD) {
            #pragma unroll 16
            for (int k = 0; k < m; k++)
                acc = __fadd_rn(acc, buf[s][k][t]);
        }
        __syncthreads();
    }
    #undef LOAD_TILE

    // ---- fused center update (fp ops identical to reference order) ----
    float* scr = &buf[0][0][0];
    if (t < FD) {
        float oldc = g_centers[cl * FD + t];
        float cntf = (float)n;
        float den  = fmaxf(cntf, 1.0f);
        float mval = __fdiv_rn(acc, den);
        float nc   = (cntf > 0.0f) ? mval : oldc;
        float d    = nc - oldc;
        g_centers[cl * FD + t] = nc;
        scr[t] = d;
    }
    if (t == 8) g_counts[cl] = 0;   // reset this cluster's gate accumulator
    __syncthreads();
    if (t == 0) {
        float dsq = 0.0f;
        #pragma unroll
        for (int k = 0; k < FD; k++)
            dsq = __fadd_rn(dsq, __fmul_rn(scr[k], scr[k]));
        g_dsq[cl] = dsq;
    }

    // ---- convergence (last block via ticket, exact tree order) ----
    __threadfence();
    __syncthreads();
    int* iscr = (int*)scr;
    if (t == 0) {
        int old = atomicAdd(&g_ticket2, 1);
        iscr[16] = (old == NUM - 1);
    }
    __syncthreads();
    if (iscr[16]) {
        float* red = scr + 64;
        if (t < NUM) red[t] = g_dsq[t];
        __syncthreads();
        #pragma unroll
        for (int s2 = 64; s2 > 0; s2 >>= 1) {
            if (t < s2) red[t] += red[t + s2];
            __syncthreads();
        }
        if (t == 0) {
            if (red[0] < THRESH2) g_converged = 1;
            g_ticket2 = 0;
        }
    }
}

// ------------------------------------------------------------------
// Output: [ labels as float (N) | centers (NUM*FD) ], float32
__global__ void __launch_bounds__(256) outputKernel(float* __restrict__ out, int out_size) {
    int idx = blockIdx.x * 256 + threadIdx.x;
    if (idx < N_PTS && idx < out_size)
        out[idx] = (float)g_labels[idx];
    if (idx < NUM * FD && (N_PTS + idx) < out_size)
        out[N_PTS + idx] = g_centers[idx];
}

// ------------------------------------------------------------------
extern "C" void kernel_launch(void* const* d_in, const int* in_sizes, int n_in,
                              void* d_out, int out_size) {
    const float* data    = (const float*)d_in[0];
    const float* centers = (const float*)d_in[1];

    // Y0 = largest f32 y with sqrt_rn(y) <= r, r = 0.32f.
    float  r  = 0.32f;
    double m  = 0.5 * ((double)r + (double)nextafterf(r, 2.0f));
    double m2 = m * m;
    float  Y0 = (float)m2;
    if ((double)Y0 >= m2) Y0 = nextafterf(Y0, 0.0f);

    // Fused init + pack + iteration-0 count + cell histogram
    countKernel0<<<NBLK, 256>>>(data, centers, Y0);
    cellScanKernel<<<1, 1024>>>();
    cellScatterKernel<<<NBLK, 256>>>();
    for (int it = 0; it < MAXIT; it++) {
        assignKernel<<<NBLK, 256>>>(data, Y0);   // spatially-coherent warps
        scanKernel<<<NUM, 128>>>();              // + fused base scan + hist reset
        scatterKernel<<<NBLK, 256>>>();
        segsumKernel<<<NUM, TPB_SEG>>>(data);    // + fused update/convergence/reset
        if (it < MAXIT - 1) countKernel<<<NBLK, 256>>>(Y0);
    }
    outputKernel<<<NBLK, 256>>>((float*)d_out, out_size);
}